// round 2
// baseline (speedup 1.0000x reference)
#include <cuda_runtime.h>

#define ETA_MIN 0.6931471805599453f
#define ETA_MAX 10.0f

// out[i] = loss[i] > eta ? 0 : 1 - loss[i]/eta,  eta = clamp(eta_value[0], ln2, 10)
// Pure streaming kernel: 128MB read + 128MB write, zero reuse.
// Persistent grid-stride, 4 independent float4 loads per iteration (MLP=4),
// streaming cache hints to avoid L2 thrash.

__device__ __forceinline__ float4 weight4(float4 a, float eta, float inv_eta) {
    float4 r;
    r.x = (a.x > eta) ? 0.0f : fmaf(-a.x, inv_eta, 1.0f);
    r.y = (a.y > eta) ? 0.0f : fmaf(-a.y, inv_eta, 1.0f);
    r.z = (a.z > eta) ? 0.0f : fmaf(-a.z, inv_eta, 1.0f);
    r.w = (a.w > eta) ? 0.0f : fmaf(-a.w, inv_eta, 1.0f);
    return r;
}

__global__ __launch_bounds__(512) void weights_kernel(
    const float4* __restrict__ loss4,
    const float* __restrict__ eta_value,
    float4* __restrict__ out4,
    int n4)
{
    float eta = eta_value[0];
    eta = fminf(fmaxf(eta, ETA_MIN), ETA_MAX);
    float inv_eta = 1.0f / eta;

    const int nthreads = gridDim.x * blockDim.x;
    const int tid = blockIdx.x * blockDim.x + threadIdx.x;
    // Each iteration covers 4*nthreads float4 elements.
    const int chunk = nthreads * 4;

    int i = tid;
    // Main loop: 4 fully-resident independent LDG.128 per thread per iter.
    for (; i + 3 * nthreads < n4; i += chunk) {
        float4 a0 = __ldcs(&loss4[i]);
        float4 a1 = __ldcs(&loss4[i + nthreads]);
        float4 a2 = __ldcs(&loss4[i + 2 * nthreads]);
        float4 a3 = __ldcs(&loss4[i + 3 * nthreads]);

        __stcs(&out4[i],                weight4(a0, eta, inv_eta));
        __stcs(&out4[i + nthreads],     weight4(a1, eta, inv_eta));
        __stcs(&out4[i + 2 * nthreads], weight4(a2, eta, inv_eta));
        __stcs(&out4[i + 3 * nthreads], weight4(a3, eta, inv_eta));
    }
    // Remainder (guarded, same coalesced pattern).
    for (; i < n4; i += nthreads) {
        float4 a = __ldcs(&loss4[i]);
        __stcs(&out4[i], weight4(a, eta, inv_eta));
    }
}

// Scalar tail for n % 4 != 0 (not hit for N=2^25, kept for generality).
__global__ void weights_tail_kernel(
    const float* __restrict__ loss,
    const float* __restrict__ eta_value,
    float* __restrict__ out,
    int start, int n)
{
    int i = start + blockIdx.x * blockDim.x + threadIdx.x;
    if (i < n) {
        float eta = eta_value[0];
        eta = fminf(fmaxf(eta, ETA_MIN), ETA_MAX);
        float v = loss[i];
        out[i] = (v > eta) ? 0.0f : 1.0f - v / eta;
    }
}

extern "C" void kernel_launch(void* const* d_in, const int* in_sizes, int n_in,
                              void* d_out, int out_size)
{
    const float* loss = (const float*)d_in[0];
    const float* eta_value = (const float*)d_in[1];
    float* out = (float*)d_out;
    int n = in_sizes[0];

    int n4 = n / 4;
    int vec_elems = n4 * 4;

    // Persistent grid: 4 CTAs/SM x 148 SMs (152 on GB300; 592 still divides work well).
    const int threads = 512;
    const int blocks = 592;

    if (n4 > 0) {
        weights_kernel<<<blocks, threads>>>(
            (const float4*)loss, eta_value, (float4*)out, n4);
    }
    int tail = n - vec_elems;
    if (tail > 0) {
        int tb = (tail + 255) / 256;
        weights_tail_kernel<<<tb, 256>>>(loss, eta_value, out, vec_elems, n);
    }
}

// round 3
// speedup vs baseline: 1.1137x; 1.1137x over previous
#include <cuda_runtime.h>

#define ETA_MIN 0.6931471805599453f
#define ETA_MAX 10.0f

// out[i] = loss[i] > eta ? 0 : 1 - loss[i]/eta,  eta = clamp(eta_value[0], ln2, 10)
// Flat grid (R1 structure), 4 independent float4 loads per thread (MLP_p1=4),
// DEFAULT cache operators (the .cs hints in R2 regressed DRAM efficiency).

__device__ __forceinline__ float4 weight4(float4 a, float eta, float inv_eta) {
    float4 r;
    r.x = (a.x > eta) ? 0.0f : fmaf(-a.x, inv_eta, 1.0f);
    r.y = (a.y > eta) ? 0.0f : fmaf(-a.y, inv_eta, 1.0f);
    r.z = (a.z > eta) ? 0.0f : fmaf(-a.z, inv_eta, 1.0f);
    r.w = (a.w > eta) ? 0.0f : fmaf(-a.w, inv_eta, 1.0f);
    return r;
}

__global__ __launch_bounds__(256) void weights_kernel(
    const float4* __restrict__ loss4,
    const float* __restrict__ eta_value,
    float4* __restrict__ out4,
    int n4)
{
    float eta = eta_value[0];
    eta = fminf(fmaxf(eta, ETA_MIN), ETA_MAX);
    float inv_eta = 1.0f / eta;

    // Block-tiled: each block covers 1024 consecutive float4 (64KB in, 64KB out).
    // Per-warp accesses stay fully coalesced; 4 loads batched up front -> MLP_p1=4.
    int base = blockIdx.x * (blockDim.x * 4) + threadIdx.x;

    if (base + 3 * 256 < n4) {
        // Fast path: all four in range (always true except possibly last block).
        float4 a0 = loss4[base];
        float4 a1 = loss4[base + 256];
        float4 a2 = loss4[base + 512];
        float4 a3 = loss4[base + 768];

        out4[base]       = weight4(a0, eta, inv_eta);
        out4[base + 256] = weight4(a1, eta, inv_eta);
        out4[base + 512] = weight4(a2, eta, inv_eta);
        out4[base + 768] = weight4(a3, eta, inv_eta);
    } else {
        #pragma unroll
        for (int k = 0; k < 4; k++) {
            int idx = base + k * 256;
            if (idx < n4) {
                float4 a = loss4[idx];
                out4[idx] = weight4(a, eta, inv_eta);
            }
        }
    }
}

// Scalar tail for n % 4 != 0 (not hit for N=2^25; kept for generality).
__global__ void weights_tail_kernel(
    const float* __restrict__ loss,
    const float* __restrict__ eta_value,
    float* __restrict__ out,
    int start, int n)
{
    int i = start + blockIdx.x * blockDim.x + threadIdx.x;
    if (i < n) {
        float eta = eta_value[0];
        eta = fminf(fmaxf(eta, ETA_MIN), ETA_MAX);
        float v = loss[i];
        out[i] = (v > eta) ? 0.0f : 1.0f - v / eta;
    }
}

extern "C" void kernel_launch(void* const* d_in, const int* in_sizes, int n_in,
                              void* d_out, int out_size)
{
    const float* loss = (const float*)d_in[0];
    const float* eta_value = (const float*)d_in[1];
    float* out = (float*)d_out;
    int n = in_sizes[0];

    int n4 = n / 4;
    int vec_elems = n4 * 4;

    const int threads = 256;
    const int per_block = threads * 4;  // 1024 float4 per block
    int blocks = (n4 + per_block - 1) / per_block;  // 8192 for N=2^25

    if (blocks > 0) {
        weights_kernel<<<blocks, threads>>>(
            (const float4*)loss, eta_value, (float4*)out, n4);
    }
    int tail = n - vec_elems;
    if (tail > 0) {
        int tb = (tail + 255) / 256;
        weights_tail_kernel<<<tb, 256>>>(loss, eta_value, out, vec_elems, n);
    }
}